// round 2
// baseline (speedup 1.0000x reference)
#include <cuda_runtime.h>
#include <cuda_bf16.h>

#define NTHREADS 320

// bf16 weight copies (filled by convert kernel each launch). uint4 for 16B alignment.
__device__ uint4 g_w2b[9 * 2048];  // 9 taps x 128ci x 128co bf16 = 32KB/tap
__device__ uint4 g_w3b[9 * 1024];  // 9 taps x 128ci x 64co  bf16 = 16KB/tap
__device__ uint4 g_w4b[9 * 512];   // 9 taps x  64ci x 64co  bf16 =  8KB/tap

__global__ void convert_weights_kernel(const float* __restrict__ w2,
                                       const float* __restrict__ w3,
                                       const float* __restrict__ w4) {
    const int n2 = 9 * 128 * 128;
    const int n3 = 9 * 128 * 64;
    const int n4 = 9 * 64 * 64;
    __nv_bfloat16* p2 = (__nv_bfloat16*)g_w2b;
    __nv_bfloat16* p3 = (__nv_bfloat16*)g_w3b;
    __nv_bfloat16* p4 = (__nv_bfloat16*)g_w4b;
    int stride = gridDim.x * blockDim.x;
    int gid = blockIdx.x * blockDim.x + threadIdx.x;
    for (int i = gid; i < n2; i += stride) p2[i] = __float2bfloat16(w2[i]);
    for (int i = gid; i < n3; i += stride) p3[i] = __float2bfloat16(w3[i]);
    for (int i = gid; i < n4; i += stride) p4[i] = __float2bfloat16(w4[i]);
}

// SMEM layout (bytes)
#define OFF_HEAD 0                       // 512B: img[100] floats, later feat/h/s
#define OFF_ACT1 512                     // 128 * 101 * 4 = 51712  (act1; later partial[4*64*25]=25600 + act3@+25600)
#define ACT1_STRIDE 101
#define OFF_WT   (OFF_ACT1 + 128 * ACT1_STRIDE * 4)   // 52224, 32768B weight-tap buffer
#define OFF_P2   (OFF_WT + 32768)                      // 84992, pooled2 / act4: 128*25*4 = 12800
#define SMEM_TOTAL (OFF_P2 + 12800)                    // 97792

__global__ __launch_bounds__(NTHREADS, 2)
void img2svg_kernel(const float* __restrict__ data,
                    const float* __restrict__ w1, const float* __restrict__ b1,
                    const float* __restrict__ b2,
                    const float* __restrict__ b3,
                    const float* __restrict__ b4,
                    const float* __restrict__ wd1, const float* __restrict__ bd1,
                    const float* __restrict__ wd2, const float* __restrict__ bd2,
                    float* __restrict__ out) {
    extern __shared__ char smem[];
    float* head    = (float*)(smem + OFF_HEAD);
    float* act1    = (float*)(smem + OFF_ACT1);              // [128][101] (100 used)
    __nv_bfloat16* wt = (__nv_bfloat16*)(smem + OFF_WT);
    float* pooled2 = (float*)(smem + OFF_P2);                // [128][25]
    float* partial = act1;                                   // [4][64][25] overlay (act1 dead)
    float* act3    = (float*)(smem + OFF_ACT1 + 25600);      // [64][25]
    float* act4    = pooled2;                                // [64][25] overlay (pooled2 dead)

    const int tid = threadIdx.x;
    const int b = blockIdx.x;

    // ---- load image ----
    float* img = head;  // 100 floats
    if (tid < 100) img[tid] = data[b * 100 + tid];
    __syncthreads();

    // ---- conv1: 1 -> 128, relu ----
    if (tid < 256) {
        const int c = tid & 127;
        const int half = tid >> 7;
        float wv[9];
        #pragma unroll
        for (int t = 0; t < 9; t++) wv[t] = w1[t * 128 + c];
        const float bias = b1[c];
        for (int r = half * 5; r < half * 5 + 5; ++r) {
            #pragma unroll
            for (int j = 0; j < 10; ++j) {
                float acc = bias;
                #pragma unroll
                for (int dy = -1; dy <= 1; dy++) {
                    int rr = r + dy;
                    if ((unsigned)rr < 10u) {
                        #pragma unroll
                        for (int dx = -1; dx <= 1; dx++) {
                            int jc = j + dx;
                            if ((unsigned)jc < 10u)
                                acc += wv[(dy + 1) * 3 + (dx + 1)] * img[rr * 10 + jc];
                        }
                    }
                }
                act1[c * ACT1_STRIDE + r * 10 + j] = fmaxf(acc, 0.f);
            }
        }
    }
    __syncthreads();

    // ---- conv2: 128 -> 128, relu, then 2x2 maxpool -> pooled2[128][5][5] ----
    {
        const int cg = tid & 31;      // 32 channel groups of 4
        const int rg = tid >> 5;      // 10 rows, one per warp
        const int c0 = cg * 4;
        float acc[4][10];
        #pragma unroll
        for (int k = 0; k < 4; k++) {
            float bb = b2[c0 + k];
            #pragma unroll
            for (int j = 0; j < 10; j++) acc[k][j] = bb;
        }
        #pragma unroll
        for (int tap = 0; tap < 9; ++tap) {
            const int dy = tap / 3 - 1, dx = tap % 3 - 1;
            __syncthreads();
            {   // stage 32KB bf16 weight slice for this tap
                const uint4* src = g_w2b + tap * 2048;
                uint4* dst = (uint4*)wt;
                for (int i = tid; i < 2048; i += NTHREADS) dst[i] = src[i];
            }
            __syncthreads();
            const int rr = rg + dy;
            if ((unsigned)rr < 10u) {
                const float* arow = act1 + rr * 10 + dx;
                const char* wbase = (const char*)wt + c0 * 2;
                for (int ci = 0; ci < 128; ++ci) {
                    uint2 wraw = *(const uint2*)(wbase + ci * 256);
                    float2 w01 = __bfloat1622float2(*(const __nv_bfloat162*)&wraw.x);
                    float2 w23 = __bfloat1622float2(*(const __nv_bfloat162*)&wraw.y);
                    const float* ap = arow + ci * ACT1_STRIDE;
                    #pragma unroll
                    for (int j = 0; j < 10; j++) {
                        if ((unsigned)(j + dx) < 10u) {
                            float a = ap[j];
                            acc[0][j] += w01.x * a;
                            acc[1][j] += w01.y * a;
                            acc[2][j] += w23.x * a;
                            acc[3][j] += w23.y * a;
                        }
                    }
                }
            }
        }
        // relu + column-pair max
        float m[4][5];
        #pragma unroll
        for (int k = 0; k < 4; k++)
            #pragma unroll
            for (int pc = 0; pc < 5; pc++)
                m[k][pc] = fmaxf(fmaxf(acc[k][2 * pc], acc[k][2 * pc + 1]), 0.f);
        __syncthreads();
        const int pr = rg >> 1;
        if ((rg & 1) == 0) {
            #pragma unroll
            for (int k = 0; k < 4; k++)
                #pragma unroll
                for (int pc = 0; pc < 5; pc++)
                    pooled2[(c0 + k) * 25 + pr * 5 + pc] = m[k][pc];
        }
        __syncthreads();
        if (rg & 1) {
            #pragma unroll
            for (int k = 0; k < 4; k++)
                #pragma unroll
                for (int pc = 0; pc < 5; pc++) {
                    int idx = (c0 + k) * 25 + pr * 5 + pc;
                    pooled2[idx] = fmaxf(pooled2[idx], m[k][pc]);
                }
        }
        __syncthreads();
    }

    // ---- conv3: 128 -> 64 on 5x5, relu (K split 4 ways, smem reduction) ----
    {
        const int cg = tid & 15;           // 16 cgroups of 4 -> 64 channels
        const int r = (tid >> 4) % 5;      // 5 rows
        const int kg = tid / 80;           // 4 K-groups (ci 32 each)
        const int c0 = cg * 4;
        float acc[4][5];
        #pragma unroll
        for (int k = 0; k < 4; k++)
            #pragma unroll
            for (int j = 0; j < 5; j++) acc[k][j] = 0.f;
        #pragma unroll
        for (int tap = 0; tap < 9; ++tap) {
            const int dy = tap / 3 - 1, dx = tap % 3 - 1;
            __syncthreads();
            {
                const uint4* src = g_w3b + tap * 1024;
                uint4* dst = (uint4*)wt;
                for (int i = tid; i < 1024; i += NTHREADS) dst[i] = src[i];
            }
            __syncthreads();
            const int rr = r + dy;
            if ((unsigned)rr < 5u) {
                const char* wbase = (const char*)wt + c0 * 2;
                for (int ci = kg * 32; ci < kg * 32 + 32; ++ci) {
                    uint2 wraw = *(const uint2*)(wbase + ci * 128);
                    float2 w01 = __bfloat1622float2(*(const __nv_bfloat162*)&wraw.x);
                    float2 w23 = __bfloat1622float2(*(const __nv_bfloat162*)&wraw.y);
                    const float* ap = pooled2 + ci * 25 + rr * 5 + dx;
                    #pragma unroll
                    for (int j = 0; j < 5; j++) {
                        if ((unsigned)(j + dx) < 5u) {
                            float a = ap[j];
                            acc[0][j] += w01.x * a;
                            acc[1][j] += w01.y * a;
                            acc[2][j] += w23.x * a;
                            acc[3][j] += w23.y * a;
                        }
                    }
                }
            }
        }
        #pragma unroll
        for (int k = 0; k < 4; k++)
            #pragma unroll
            for (int j = 0; j < 5; j++)
                partial[kg * 1600 + (c0 + k) * 25 + r * 5 + j] = acc[k][j];
        __syncthreads();
        for (int i = tid; i < 1600; i += NTHREADS) {
            int c = i / 25;
            float s = b3[c] + partial[i] + partial[1600 + i] + partial[3200 + i] + partial[4800 + i];
            act3[i] = fmaxf(s, 0.f);
        }
        __syncthreads();
    }

    // ---- conv4: 64 -> 64 on 5x5, relu ----
    {
        const int cg = tid & 15;
        const int r = (tid >> 4) % 5;
        const int kg = tid / 80;           // ci 16 each
        const int c0 = cg * 4;
        float acc[4][5];
        #pragma unroll
        for (int k = 0; k < 4; k++)
            #pragma unroll
            for (int j = 0; j < 5; j++) acc[k][j] = 0.f;
        #pragma unroll
        for (int tap = 0; tap < 9; ++tap) {
            const int dy = tap / 3 - 1, dx = tap % 3 - 1;
            __syncthreads();
            {
                const uint4* src = g_w4b + tap * 512;
                uint4* dst = (uint4*)wt;
                for (int i = tid; i < 512; i += NTHREADS) dst[i] = src[i];
            }
            __syncthreads();
            const int rr = r + dy;
            if ((unsigned)rr < 5u) {
                const char* wbase = (const char*)wt + c0 * 2;
                for (int ci = kg * 16; ci < kg * 16 + 16; ++ci) {
                    uint2 wraw = *(const uint2*)(wbase + ci * 128);
                    float2 w01 = __bfloat1622float2(*(const __nv_bfloat162*)&wraw.x);
                    float2 w23 = __bfloat1622float2(*(const __nv_bfloat162*)&wraw.y);
                    const float* ap = act3 + ci * 25 + rr * 5 + dx;
                    #pragma unroll
                    for (int j = 0; j < 5; j++) {
                        if ((unsigned)(j + dx) < 5u) {
                            float a = ap[j];
                            acc[0][j] += w01.x * a;
                            acc[1][j] += w01.y * a;
                            acc[2][j] += w23.x * a;
                            acc[3][j] += w23.y * a;
                        }
                    }
                }
            }
        }
        #pragma unroll
        for (int k = 0; k < 4; k++)
            #pragma unroll
            for (int j = 0; j < 5; j++)
                partial[kg * 1600 + (c0 + k) * 25 + r * 5 + j] = acc[k][j];
        __syncthreads();
        for (int i = tid; i < 1600; i += NTHREADS) {
            int c = i / 25;
            float s = b4[c] + partial[i] + partial[1600 + i] + partial[3200 + i] + partial[4800 + i];
            act4[i] = fmaxf(s, 0.f);
        }
        __syncthreads();
    }

    // ---- pool 2x2 -> 2x2, mean, dense head, svg ----
    float* feat = head;        // 64
    float* hvec = head + 64;   // 32
    float* svec = head + 96;   // 4
    if (tid < 64) {
        const float* a = act4 + tid * 25;
        float m00 = fmaxf(fmaxf(a[0], a[1]), fmaxf(a[5], a[6]));
        float m01 = fmaxf(fmaxf(a[2], a[3]), fmaxf(a[7], a[8]));
        float m10 = fmaxf(fmaxf(a[10], a[11]), fmaxf(a[15], a[16]));
        float m11 = fmaxf(fmaxf(a[12], a[13]), fmaxf(a[17], a[18]));
        feat[tid] = 0.25f * (m00 + m01 + m10 + m11);
    }
    __syncthreads();
    if (tid < 32) {
        float accd = bd1[tid];
        for (int c = 0; c < 64; c++) accd += feat[c] * wd1[c * 32 + tid];
        hvec[tid] = fmaxf(accd, 0.f);
    }
    __syncthreads();
    if (tid < 4) {
        float accd = bd2[tid];
        for (int i = 0; i < 32; i++) accd += hvec[i] * wd2[i * 4 + tid];
        svec[tid] = 1.f / (1.f + expf(-accd));
    }
    __syncthreads();
    if (tid == 0) {
        const float p1x = svec[0], p1y = svec[1], p2x = svec[2], p2y = svec[3];
        float px[5], py[5], pos[5];
        #pragma unroll
        for (int i = 0; i < 5; i++) {
            float t = 0.25f * (float)i;
            float x = ((1.f - t) * p1x + t * p2x) * 10.f;
            float y = ((1.f - t) * p1y + t * p2y) * 10.f;
            x = rintf(x);   // round-half-even, matches jnp.round
            y = rintf(y);
            px[i] = x; py[i] = y;
            pos[i] = x * 10.f + y;
        }
        // stable insertion sort by pos
        int ord[5] = {0, 1, 2, 3, 4};
        for (int i = 1; i < 5; i++) {
            int key = ord[i];
            float kp = pos[key];
            int j = i - 1;
            while (j >= 0 && pos[ord[j]] > kp) { ord[j + 1] = ord[j]; j--; }
            ord[j + 1] = key;
        }
        float ox[5], oy[5];
        #pragma unroll
        for (int i = 0; i < 5; i++) { ox[i] = px[ord[i]]; oy[i] = py[ord[i]]; }
        float o[10];
        #pragma unroll
        for (int i = 0; i < 10; i++) o[i] = -1.f;
        o[0] = ox[0]; o[1] = oy[0];
        int dst = 1;
        for (int i = 1; i < 5; i++) {
            float d = fabsf(ox[i] - ox[i - 1]) + fabsf(oy[i] - oy[i - 1]);
            if (d != 0.f) { o[2 * dst] = ox[i]; o[2 * dst + 1] = oy[i]; dst++; }
        }
        float* op = out + b * 10;
        #pragma unroll
        for (int i = 0; i < 10; i++) op[i] = o[i];
    }
}

extern "C" void kernel_launch(void* const* d_in, const int* in_sizes, int n_in,
                              void* d_out, int out_size) {
    const float* data = (const float*)d_in[0];
    const float* w1   = (const float*)d_in[1];
    const float* b1   = (const float*)d_in[2];
    const float* w2   = (const float*)d_in[3];
    const float* b2   = (const float*)d_in[4];
    const float* w3   = (const float*)d_in[5];
    const float* b3   = (const float*)d_in[6];
    const float* w4   = (const float*)d_in[7];
    const float* b4   = (const float*)d_in[8];
    const float* wd1  = (const float*)d_in[9];
    const float* bd1  = (const float*)d_in[10];
    const float* wd2  = (const float*)d_in[11];
    const float* bd2  = (const float*)d_in[12];
    float* out = (float*)d_out;
    const int B = in_sizes[0] / 100;

    cudaFuncSetAttribute(img2svg_kernel, cudaFuncAttributeMaxDynamicSharedMemorySize, SMEM_TOTAL);

    convert_weights_kernel<<<96, 256>>>(w2, w3, w4);
    img2svg_kernel<<<B, NTHREADS, SMEM_TOTAL>>>(data, w1, b1, b2, b3, b4,
                                                wd1, bd1, wd2, bd2, out);
}

// round 3
// speedup vs baseline: 1.0014x; 1.0014x over previous
#include <cuda_runtime.h>
#include <cuda_bf16.h>

#define NTHREADS 320

// bf16 weight copies (filled by convert kernel each launch). uint4 for 16B alignment.
__device__ uint4 g_w2b[9 * 2048];  // 9 taps x 128ci x 128co bf16 = 32KB/tap
__device__ uint4 g_w3b[9 * 1024];  // 9 taps x 128ci x 64co  bf16 = 16KB/tap
__device__ uint4 g_w4b[9 * 512];   // 9 taps x  64ci x 64co  bf16 =  8KB/tap

__global__ void convert_weights_kernel(const float* __restrict__ w2,
                                       const float* __restrict__ w3,
                                       const float* __restrict__ w4) {
    const int n2 = 9 * 128 * 128;
    const int n3 = 9 * 128 * 64;
    const int n4 = 9 * 64 * 64;
    __nv_bfloat16* p2 = (__nv_bfloat16*)g_w2b;
    __nv_bfloat16* p3 = (__nv_bfloat16*)g_w3b;
    __nv_bfloat16* p4 = (__nv_bfloat16*)g_w4b;
    int stride = gridDim.x * blockDim.x;
    int gid = blockIdx.x * blockDim.x + threadIdx.x;
    for (int i = gid; i < n2; i += stride) p2[i] = __float2bfloat16(w2[i]);
    for (int i = gid; i < n3; i += stride) p3[i] = __float2bfloat16(w3[i]);
    for (int i = gid; i < n4; i += stride) p4[i] = __float2bfloat16(w4[i]);
}

// SMEM layout (bytes)
#define OFF_HEAD 0                       // 512B: img[100] floats, later feat/h/s
#define OFF_ACT1 512                     // 128 * 101 * 4 = 51712  (act1; later partial[4*64*25]=25600 + act3@+25600)
#define ACT1_STRIDE 101
#define OFF_WT   (OFF_ACT1 + 128 * ACT1_STRIDE * 4)   // 52224, 32768B weight-tap buffer
#define OFF_P2   (OFF_WT + 32768)                      // 84992, pooled2 / act4: 128*25*4 = 12800
#define SMEM_TOTAL (OFF_P2 + 12800)                    // 97792

__global__ __launch_bounds__(NTHREADS, 2)
void img2svg_kernel(const float* __restrict__ data,
                    const float* __restrict__ w1, const float* __restrict__ b1,
                    const float* __restrict__ b2,
                    const float* __restrict__ b3,
                    const float* __restrict__ b4,
                    const float* __restrict__ wd1, const float* __restrict__ bd1,
                    const float* __restrict__ wd2, const float* __restrict__ bd2,
                    float* __restrict__ out) {
    extern __shared__ char smem[];
    float* head    = (float*)(smem + OFF_HEAD);
    float* act1    = (float*)(smem + OFF_ACT1);              // [128][101] (100 used)
    __nv_bfloat16* wt = (__nv_bfloat16*)(smem + OFF_WT);
    float* pooled2 = (float*)(smem + OFF_P2);                // [128][25]
    float* partial = act1;                                   // [4][64][25] overlay (act1 dead)
    float* act3    = (float*)(smem + OFF_ACT1 + 25600);      // [64][25]
    float* act4    = pooled2;                                // [64][25] overlay (pooled2 dead)

    const int tid = threadIdx.x;
    const int b = blockIdx.x;

    // ---- load image ----
    float* img = head;  // 100 floats
    if (tid < 100) img[tid] = data[b * 100 + tid];
    __syncthreads();

    // ---- conv1: 1 -> 128, relu ----
    if (tid < 256) {
        const int c = tid & 127;
        const int half = tid >> 7;
        float wv[9];
        #pragma unroll
        for (int t = 0; t < 9; t++) wv[t] = w1[t * 128 + c];
        const float bias = b1[c];
        for (int r = half * 5; r < half * 5 + 5; ++r) {
            #pragma unroll
            for (int j = 0; j < 10; ++j) {
                float acc = bias;
                #pragma unroll
                for (int dy = -1; dy <= 1; dy++) {
                    int rr = r + dy;
                    if ((unsigned)rr < 10u) {
                        #pragma unroll
                        for (int dx = -1; dx <= 1; dx++) {
                            int jc = j + dx;
                            if ((unsigned)jc < 10u)
                                acc += wv[(dy + 1) * 3 + (dx + 1)] * img[rr * 10 + jc];
                        }
                    }
                }
                act1[c * ACT1_STRIDE + r * 10 + j] = fmaxf(acc, 0.f);
            }
        }
    }
    __syncthreads();

    // ---- conv2: 128 -> 128, relu, then 2x2 maxpool -> pooled2[128][5][5] ----
    {
        const int cg = tid & 31;      // 32 channel groups of 4
        const int rg = tid >> 5;      // 10 rows, one per warp
        const int c0 = cg * 4;
        float acc[4][10];
        #pragma unroll
        for (int k = 0; k < 4; k++) {
            float bb = b2[c0 + k];
            #pragma unroll
            for (int j = 0; j < 10; j++) acc[k][j] = bb;
        }
        #pragma unroll
        for (int tap = 0; tap < 9; ++tap) {
            const int dy = tap / 3 - 1, dx = tap % 3 - 1;
            __syncthreads();
            {   // stage 32KB bf16 weight slice for this tap
                const uint4* src = g_w2b + tap * 2048;
                uint4* dst = (uint4*)wt;
                for (int i = tid; i < 2048; i += NTHREADS) dst[i] = src[i];
            }
            __syncthreads();
            const int rr = rg + dy;
            if ((unsigned)rr < 10u) {
                const float* arow = act1 + rr * 10 + dx;
                const char* wbase = (const char*)wt + c0 * 2;
                for (int ci = 0; ci < 128; ++ci) {
                    uint2 wraw = *(const uint2*)(wbase + ci * 256);
                    float2 w01 = __bfloat1622float2(*(const __nv_bfloat162*)&wraw.x);
                    float2 w23 = __bfloat1622float2(*(const __nv_bfloat162*)&wraw.y);
                    const float* ap = arow + ci * ACT1_STRIDE;
                    #pragma unroll
                    for (int j = 0; j < 10; j++) {
                        if ((unsigned)(j + dx) < 10u) {
                            float a = ap[j];
                            acc[0][j] += w01.x * a;
                            acc[1][j] += w01.y * a;
                            acc[2][j] += w23.x * a;
                            acc[3][j] += w23.y * a;
                        }
                    }
                }
            }
        }
        // relu + column-pair max
        float m[4][5];
        #pragma unroll
        for (int k = 0; k < 4; k++)
            #pragma unroll
            for (int pc = 0; pc < 5; pc++)
                m[k][pc] = fmaxf(fmaxf(acc[k][2 * pc], acc[k][2 * pc + 1]), 0.f);
        __syncthreads();
        const int pr = rg >> 1;
        if ((rg & 1) == 0) {
            #pragma unroll
            for (int k = 0; k < 4; k++)
                #pragma unroll
                for (int pc = 0; pc < 5; pc++)
                    pooled2[(c0 + k) * 25 + pr * 5 + pc] = m[k][pc];
        }
        __syncthreads();
        if (rg & 1) {
            #pragma unroll
            for (int k = 0; k < 4; k++)
                #pragma unroll
                for (int pc = 0; pc < 5; pc++) {
                    int idx = (c0 + k) * 25 + pr * 5 + pc;
                    pooled2[idx] = fmaxf(pooled2[idx], m[k][pc]);
                }
        }
        __syncthreads();
    }

    // ---- conv3: 128 -> 64 on 5x5, relu (K split 4 ways, smem reduction) ----
    {
        const int cg = tid & 15;           // 16 cgroups of 4 -> 64 channels
        const int r = (tid >> 4) % 5;      // 5 rows
        const int kg = tid / 80;           // 4 K-groups (ci 32 each)
        const int c0 = cg * 4;
        float acc[4][5];
        #pragma unroll
        for (int k = 0; k < 4; k++)
            #pragma unroll
            for (int j = 0; j < 5; j++) acc[k][j] = 0.f;
        #pragma unroll
        for (int tap = 0; tap < 9; ++tap) {
            const int dy = tap / 3 - 1, dx = tap % 3 - 1;
            __syncthreads();
            {
                const uint4* src = g_w3b + tap * 1024;
                uint4* dst = (uint4*)wt;
                for (int i = tid; i < 1024; i += NTHREADS) dst[i] = src[i];
            }
            __syncthreads();
            const int rr = r + dy;
            if ((unsigned)rr < 5u) {
                const char* wbase = (const char*)wt + c0 * 2;
                for (int ci = kg * 32; ci < kg * 32 + 32; ++ci) {
                    uint2 wraw = *(const uint2*)(wbase + ci * 128);
                    float2 w01 = __bfloat1622float2(*(const __nv_bfloat162*)&wraw.x);
                    float2 w23 = __bfloat1622float2(*(const __nv_bfloat162*)&wraw.y);
                    const float* ap = pooled2 + ci * 25 + rr * 5 + dx;
                    #pragma unroll
                    for (int j = 0; j < 5; j++) {
                        if ((unsigned)(j + dx) < 5u) {
                            float a = ap[j];
                            acc[0][j] += w01.x * a;
                            acc[1][j] += w01.y * a;
                            acc[2][j] += w23.x * a;
                            acc[3][j] += w23.y * a;
                        }
                    }
                }
            }
        }
        #pragma unroll
        for (int k = 0; k < 4; k++)
            #pragma unroll
            for (int j = 0; j < 5; j++)
                partial[kg * 1600 + (c0 + k) * 25 + r * 5 + j] = acc[k][j];
        __syncthreads();
        for (int i = tid; i < 1600; i += NTHREADS) {
            int c = i / 25;
            float s = b3[c] + partial[i] + partial[1600 + i] + partial[3200 + i] + partial[4800 + i];
            act3[i] = fmaxf(s, 0.f);
        }
        __syncthreads();
    }

    // ---- conv4: 64 -> 64 on 5x5, relu ----
    {
        const int cg = tid & 15;
        const int r = (tid >> 4) % 5;
        const int kg = tid / 80;           // ci 16 each
        const int c0 = cg * 4;
        float acc[4][5];
        #pragma unroll
        for (int k = 0; k < 4; k++)
            #pragma unroll
            for (int j = 0; j < 5; j++) acc[k][j] = 0.f;
        #pragma unroll
        for (int tap = 0; tap < 9; ++tap) {
            const int dy = tap / 3 - 1, dx = tap % 3 - 1;
            __syncthreads();
            {
                const uint4* src = g_w4b + tap * 512;
                uint4* dst = (uint4*)wt;
                for (int i = tid; i < 512; i += NTHREADS) dst[i] = src[i];
            }
            __syncthreads();
            const int rr = r + dy;
            if ((unsigned)rr < 5u) {
                const char* wbase = (const char*)wt + c0 * 2;
                for (int ci = kg * 16; ci < kg * 16 + 16; ++ci) {
                    uint2 wraw = *(const uint2*)(wbase + ci * 128);
                    float2 w01 = __bfloat1622float2(*(const __nv_bfloat162*)&wraw.x);
                    float2 w23 = __bfloat1622float2(*(const __nv_bfloat162*)&wraw.y);
                    const float* ap = act3 + ci * 25 + rr * 5 + dx;
                    #pragma unroll
                    for (int j = 0; j < 5; j++) {
                        if ((unsigned)(j + dx) < 5u) {
                            float a = ap[j];
                            acc[0][j] += w01.x * a;
                            acc[1][j] += w01.y * a;
                            acc[2][j] += w23.x * a;
                            acc[3][j] += w23.y * a;
                        }
                    }
                }
            }
        }
        #pragma unroll
        for (int k = 0; k < 4; k++)
            #pragma unroll
            for (int j = 0; j < 5; j++)
                partial[kg * 1600 + (c0 + k) * 25 + r * 5 + j] = acc[k][j];
        __syncthreads();
        for (int i = tid; i < 1600; i += NTHREADS) {
            int c = i / 25;
            float s = b4[c] + partial[i] + partial[1600 + i] + partial[3200 + i] + partial[4800 + i];
            act4[i] = fmaxf(s, 0.f);
        }
        __syncthreads();
    }

    // ---- pool 2x2 -> 2x2, mean, dense head, svg ----
    float* feat = head;        // 64
    float* hvec = head + 64;   // 32
    float* svec = head + 96;   // 4
    if (tid < 64) {
        const float* a = act4 + tid * 25;
        float m00 = fmaxf(fmaxf(a[0], a[1]), fmaxf(a[5], a[6]));
        float m01 = fmaxf(fmaxf(a[2], a[3]), fmaxf(a[7], a[8]));
        float m10 = fmaxf(fmaxf(a[10], a[11]), fmaxf(a[15], a[16]));
        float m11 = fmaxf(fmaxf(a[12], a[13]), fmaxf(a[17], a[18]));
        feat[tid] = 0.25f * (m00 + m01 + m10 + m11);
    }
    __syncthreads();
    if (tid < 32) {
        float accd = bd1[tid];
        for (int c = 0; c < 64; c++) accd += feat[c] * wd1[c * 32 + tid];
        hvec[tid] = fmaxf(accd, 0.f);
    }
    __syncthreads();
    if (tid < 4) {
        float accd = bd2[tid];
        for (int i = 0; i < 32; i++) accd += hvec[i] * wd2[i * 4 + tid];
        svec[tid] = 1.f / (1.f + expf(-accd));
    }
    __syncthreads();
    if (tid == 0) {
        const float p1x = svec[0], p1y = svec[1], p2x = svec[2], p2y = svec[3];
        float px[5], py[5], pos[5];
        #pragma unroll
        for (int i = 0; i < 5; i++) {
            float t = 0.25f * (float)i;
            float x = ((1.f - t) * p1x + t * p2x) * 10.f;
            float y = ((1.f - t) * p1y + t * p2y) * 10.f;
            x = rintf(x);   // round-half-even, matches jnp.round
            y = rintf(y);
            px[i] = x; py[i] = y;
            pos[i] = x * 10.f + y;
        }
        // stable insertion sort by pos
        int ord[5] = {0, 1, 2, 3, 4};
        for (int i = 1; i < 5; i++) {
            int key = ord[i];
            float kp = pos[key];
            int j = i - 1;
            while (j >= 0 && pos[ord[j]] > kp) { ord[j + 1] = ord[j]; j--; }
            ord[j + 1] = key;
        }
        float ox[5], oy[5];
        #pragma unroll
        for (int i = 0; i < 5; i++) { ox[i] = px[ord[i]]; oy[i] = py[ord[i]]; }
        float o[10];
        #pragma unroll
        for (int i = 0; i < 10; i++) o[i] = -1.f;
        o[0] = ox[0]; o[1] = oy[0];
        int dst = 1;
        for (int i = 1; i < 5; i++) {
            float d = fabsf(ox[i] - ox[i - 1]) + fabsf(oy[i] - oy[i - 1]);
            if (d != 0.f) { o[2 * dst] = ox[i]; o[2 * dst + 1] = oy[i]; dst++; }
        }
        float* op = out + b * 10;
        #pragma unroll
        for (int i = 0; i < 10; i++) op[i] = o[i];
    }
}

extern "C" void kernel_launch(void* const* d_in, const int* in_sizes, int n_in,
                              void* d_out, int out_size) {
    const float* data = (const float*)d_in[0];
    const float* w1   = (const float*)d_in[1];
    const float* b1   = (const float*)d_in[2];
    const float* w2   = (const float*)d_in[3];
    const float* b2   = (const float*)d_in[4];
    const float* w3   = (const float*)d_in[5];
    const float* b3   = (const float*)d_in[6];
    const float* w4   = (const float*)d_in[7];
    const float* b4   = (const float*)d_in[8];
    const float* wd1  = (const float*)d_in[9];
    const float* bd1  = (const float*)d_in[10];
    const float* wd2  = (const float*)d_in[11];
    const float* bd2  = (const float*)d_in[12];
    float* out = (float*)d_out;
    const int B = in_sizes[0] / 100;

    cudaFuncSetAttribute(img2svg_kernel, cudaFuncAttributeMaxDynamicSharedMemorySize, SMEM_TOTAL);

    convert_weights_kernel<<<96, 256>>>(w2, w3, w4);
    img2svg_kernel<<<B, NTHREADS, SMEM_TOTAL>>>(data, w1, b1, b2, b3, b4,
                                                wd1, bd1, wd2, bd2, out);
}

// round 5
// speedup vs baseline: 5.4160x; 5.4086x over previous
#include <cuda_runtime.h>
#include <cuda_bf16.h>
#include <cstdint>

#define NT 512

// Transposed bf16 weights in gmem: [tap][co][ci] row-major
__device__ uint4 g_w2c[9 * 2048];  // [tap][128co][128ci]
__device__ uint4 g_w3c[9 * 1024];  // [tap][64co][128ci]
__device__ uint4 g_w4c[9 * 512];   // [tap][64co][64ci]

__global__ void convert_weights(const float* __restrict__ w2,
                                const float* __restrict__ w3,
                                const float* __restrict__ w4) {
    int gid = blockIdx.x * blockDim.x + threadIdx.x;
    int stride = gridDim.x * blockDim.x;
    __nv_bfloat16* p2 = (__nv_bfloat16*)g_w2c;
    __nv_bfloat16* p3 = (__nv_bfloat16*)g_w3c;
    __nv_bfloat16* p4 = (__nv_bfloat16*)g_w4c;
    for (int i = gid; i < 9 * 128 * 128; i += stride) {
        int tap = i >> 14, rem = i & 16383, co = rem >> 7, ci = rem & 127;
        p2[i] = __float2bfloat16(w2[tap * 16384 + ci * 128 + co]);
    }
    for (int i = gid; i < 9 * 64 * 128; i += stride) {
        int tap = i >> 13, rem = i & 8191, co = rem >> 7, ci = rem & 127;
        p3[i] = __float2bfloat16(w3[tap * 8192 + ci * 64 + co]);
    }
    for (int i = gid; i < 9 * 64 * 64; i += stride) {
        int tap = i >> 12, rem = i & 4095, co = rem >> 6, ci = rem & 63;
        p4[i] = __float2bfloat16(w4[tap * 4096 + ci * 64 + co]);
    }
}

// ---------------- SMEM layout (byte offsets) ----------------
#define S_ACT1   0          // 4 x [100 pos][136 ci] bf16 (stride 272B) = 108800
#define S_WBUF   108800     // 2 x 34816 weight double-buffer = 69632
#define S_POOL2  178432     // [100][136] bf16 stride 272 = 27200
#define S_ACT3   205632     // [100][72] bf16 stride 144 = 14400
#define S_ZERO   220032     // 272 zero row
#define S_B2     220304     // 128 f32
#define S_B3     220816     // 64 f32
#define S_B4     221072     // 64 f32
#define S_BD1    221328     // 32 f32
#define S_BD2    221456     // 4 f32
#define S_WD2    221472     // 128 f32
#define S_FEAT   221984     // 4*64 f32
#define S_H      223008     // 4*32 f32
#define S_SV     223520     // 16 f32
#define S_IMG    223584     // 400 f32
#define SMEM_TOTAL 225184
#define S_ACT4   54400      // act4 scratch [64co][104n] stride 208 = 13312 (overlays act1 slot 2)

__device__ __forceinline__ void mma16816(float* c, uint32_t a0, uint32_t a1, uint32_t a2,
                                         uint32_t a3, uint32_t b0, uint32_t b1) {
    asm volatile(
        "mma.sync.aligned.m16n8k16.row.col.f32.bf16.bf16.f32 "
        "{%0,%1,%2,%3},{%4,%5,%6,%7},{%8,%9},{%0,%1,%2,%3};\n"
        : "+f"(c[0]), "+f"(c[1]), "+f"(c[2]), "+f"(c[3])
        : "r"(a0), "r"(a1), "r"(a2), "r"(a3), "r"(b0), "r"(b1));
}

// One tap: C[m32][n = NJ*8] += W[m32][k] * Act[n][k], k = KS*16
template <int NJ, int KS>
__device__ __forceinline__ void gemm_tap(const char* smp, uint32_t aw, int ws,
                                         const uint32_t* bn, float (*C0)[4], float (*C1)[4]) {
    #pragma unroll
    for (int ks = 0; ks < KS; ks++) {
        int ko = ks * 32;
        uint32_t a0 = *(const uint32_t*)(smp + aw + ko);
        uint32_t a1 = *(const uint32_t*)(smp + aw + 8 * ws + ko);
        uint32_t a2 = *(const uint32_t*)(smp + aw + ko + 16);
        uint32_t a3 = *(const uint32_t*)(smp + aw + 8 * ws + ko + 16);
        uint32_t a4 = *(const uint32_t*)(smp + aw + 16 * ws + ko);
        uint32_t a5 = *(const uint32_t*)(smp + aw + 24 * ws + ko);
        uint32_t a6 = *(const uint32_t*)(smp + aw + 16 * ws + ko + 16);
        uint32_t a7 = *(const uint32_t*)(smp + aw + 24 * ws + ko + 16);
        #pragma unroll
        for (int j = 0; j < NJ; j++) {
            uint32_t b0 = *(const uint32_t*)(smp + bn[j] + ko);
            uint32_t b1 = *(const uint32_t*)(smp + bn[j] + ko + 16);
            mma16816(C0[j], a0, a1, a2, a3, b0, b1);
            mma16816(C1[j], a4, a5, a6, a7, b0, b1);
        }
    }
}

__global__ __launch_bounds__(NT, 1)
void img2svg_mma(const float* __restrict__ data,
                 const float* __restrict__ w1, const float* __restrict__ b1,
                 const float* __restrict__ b2v, const float* __restrict__ b3v,
                 const float* __restrict__ b4v,
                 const float* __restrict__ wd1, const float* __restrict__ bd1,
                 const float* __restrict__ wd2, const float* __restrict__ bd2,
                 float* __restrict__ out, int Btot) {
    extern __shared__ char sm[];
    const int tid = threadIdx.x;
    const int wid = tid >> 5, lane = tid & 31;
    const int dlt = lane >> 2, q = lane & 3;

    float* s_b2  = (float*)(sm + S_B2);
    float* s_b3  = (float*)(sm + S_B3);
    float* s_b4  = (float*)(sm + S_B4);
    float* s_bd1 = (float*)(sm + S_BD1);
    float* s_bd2 = (float*)(sm + S_BD2);
    float* s_wd2 = (float*)(sm + S_WD2);
    float* s_feat = (float*)(sm + S_FEAT);
    float* s_h   = (float*)(sm + S_H);
    float* s_sv  = (float*)(sm + S_SV);
    float* s_img = (float*)(sm + S_IMG);

    // ---- init loads ----
    if (tid < 128) s_b2[tid] = b2v[tid];
    if (tid < 64)  s_b3[tid] = b3v[tid];
    if (tid < 64)  s_b4[tid] = b4v[tid];
    if (tid < 32)  s_bd1[tid] = bd1[tid];
    if (tid < 4)   s_bd2[tid] = bd2[tid];
    if (tid < 128) s_wd2[tid] = wd2[tid];
    if (tid < 68)  *(uint32_t*)(sm + S_ZERO + tid * 4) = 0u;
    {
        long long base = (long long)blockIdx.x * 400;
        for (int e = tid; e < 400; e += NT) {
            long long gi = base + e;
            s_img[e] = (gi < (long long)Btot * 100) ? data[gi] : 0.f;
        }
    }
    __syncthreads();

    // ---- conv1 (scalar): 1 -> 128, relu -> act1[img][pos][ci] bf16 ----
    {
        const int img = tid >> 7, co = tid & 127;
        const float* ip = s_img + img * 100;
        float wv[9];
        #pragma unroll
        for (int t = 0; t < 9; t++) wv[t] = w1[t * 128 + co];
        const float bias = b1[co];
        for (int pos = 0; pos < 100; pos++) {
            int r = pos / 10, c = pos - r * 10;
            float acc = bias;
            #pragma unroll
            for (int dy = -1; dy <= 1; dy++) {
                int rr = r + dy;
                if ((unsigned)rr < 10u) {
                    #pragma unroll
                    for (int dx = -1; dx <= 1; dx++) {
                        int cc = c + dx;
                        if ((unsigned)cc < 10u)
                            acc += wv[(dy + 1) * 3 + dx + 1] * ip[rr * 10 + cc];
                    }
                }
            }
            *(__nv_bfloat16*)(sm + S_ACT1 + (img * 100 + pos) * 272 + co * 2) =
                __float2bfloat16(fmaxf(acc, 0.f));
        }
    }
    __syncthreads();

    // ---- conv2: per pass 2 images x 8 warps, warp tile m32 x n64, K=128/tap ----
    for (int p = 0; p < 2; p++) {
        const int w8 = wid & 7;
        const int my_img = p * 2 + (wid >> 3);
        const int mg = w8 >> 1, ng = w8 & 1;
        const uint32_t awlane = (uint32_t)((mg * 32 + dlt) * 272 + 4 * q);
        float C0[8][4], C1[8][4];
        #pragma unroll
        for (int j = 0; j < 8; j++)
            #pragma unroll
            for (int k = 0; k < 4; k++) { C0[j][k] = 0.f; C1[j][k] = 0.f; }

        uint4 wreg[4];
        #pragma unroll
        for (int jj = 0; jj < 4; jj++) wreg[jj] = g_w2c[tid + 512 * jj];
        #pragma unroll
        for (int jj = 0; jj < 4; jj++) {
            int u = tid + 512 * jj;
            *(uint4*)(sm + S_WBUF + (u >> 4) * 272 + (u & 15) * 16) = wreg[jj];
        }
        __syncthreads();

        for (int t = 0; t < 9; t++) {
            if (t < 8) {
                #pragma unroll
                for (int jj = 0; jj < 4; jj++)
                    wreg[jj] = g_w2c[(t + 1) * 2048 + tid + 512 * jj];
            }
            const int dy = t / 3 - 1, dx = t % 3 - 1;
            uint32_t bn[8];
            #pragma unroll
            for (int j = 0; j < 8; j++) {
                int n = ng * 64 + j * 8 + dlt;
                int r = n / 10, c = n - r * 10;
                int rr = r + dy, cc = c + dx;
                bool ok = (n < 100) && ((unsigned)rr < 10u) && ((unsigned)cc < 10u);
                bn[j] = ok ? (uint32_t)(S_ACT1 + (my_img * 100 + rr * 10 + cc) * 272 + 4 * q)
                           : (uint32_t)(S_ZERO + 4 * q);
            }
            gemm_tap<8, 8>(sm, (uint32_t)(S_WBUF + (t & 1) * 34816) + awlane, 272, bn, C0, C1);
            if (t < 8) {
                uint32_t wb = S_WBUF + ((t + 1) & 1) * 34816;
                #pragma unroll
                for (int jj = 0; jj < 4; jj++) {
                    int u = tid + 512 * jj;
                    *(uint4*)(sm + wb + (u >> 4) * 272 + (u & 15) * 16) = wreg[jj];
                }
            }
            __syncthreads();
        }

        // epilogue: bias+relu -> scratch [co][104 n] (overlays act1 slot of my_img)
        const uint32_t scr = S_ACT1 + (uint32_t)my_img * 27200;
        #pragma unroll
        for (int mt = 0; mt < 2; mt++) {
            #pragma unroll
            for (int j = 0; j < 8; j++) {
                float* c = mt ? C1[j] : C0[j];
                int co = mg * 32 + mt * 16 + dlt;
                int n0 = ng * 64 + j * 8 + 2 * q;
                if (n0 < 100) {
                    float bA = s_b2[co], bB = s_b2[co + 8];
                    __nv_bfloat162 v01 = __floats2bfloat162_rn(fmaxf(c[0] + bA, 0.f),
                                                               fmaxf(c[1] + bA, 0.f));
                    __nv_bfloat162 v23 = __floats2bfloat162_rn(fmaxf(c[2] + bB, 0.f),
                                                               fmaxf(c[3] + bB, 0.f));
                    *(uint32_t*)(sm + scr + co * 208 + n0 * 2) = *(uint32_t*)&v01;
                    *(uint32_t*)(sm + scr + (co + 8) * 208 + n0 * 2) = *(uint32_t*)&v23;
                }
            }
        }
        __syncthreads();
        // 2x2 maxpool -> pooled2[img*25+p][ci]
        {
            int t8 = (wid & 7) * 32 + lane;
            for (int e = t8; e < 3200; e += 256) {
                int co = e & 127, pp = e >> 7;
                int pr = pp / 5, pc = pp - pr * 5;
                int ntop = pr * 20 + pc * 2;
                uint32_t topw = *(uint32_t*)(sm + scr + co * 208 + ntop * 2);
                uint32_t botw = *(uint32_t*)(sm + scr + co * 208 + (ntop + 10) * 2);
                float2 tf = __bfloat1622float2(*(__nv_bfloat162*)&topw);
                float2 bf = __bfloat1622float2(*(__nv_bfloat162*)&botw);
                float m = fmaxf(fmaxf(tf.x, tf.y), fmaxf(bf.x, bf.y));
                *(__nv_bfloat16*)(sm + S_POOL2 + (my_img * 25 + pp) * 272 + co * 2) =
                    __float2bfloat16(m);
            }
        }
        __syncthreads();
    }

    // ---- conv3: M=64, N=100 (4img x 25pos), K=128/tap; warps 0..7 m32n32 ----
    {
        const int mg = (wid & 7) >> 2, ng = wid & 3;
        const uint32_t awlane = (uint32_t)((mg * 32 + dlt) * 272 + 4 * q);
        float D0[4][4], D1[4][4];
        #pragma unroll
        for (int j = 0; j < 4; j++)
            #pragma unroll
            for (int k = 0; k < 4; k++) { D0[j][k] = 0.f; D1[j][k] = 0.f; }

        uint4 wreg[2];
        #pragma unroll
        for (int jj = 0; jj < 2; jj++) wreg[jj] = g_w3c[tid + 512 * jj];
        #pragma unroll
        for (int jj = 0; jj < 2; jj++) {
            int u = tid + 512 * jj;
            *(uint4*)(sm + S_WBUF + (u >> 4) * 272 + (u & 15) * 16) = wreg[jj];
        }
        __syncthreads();

        for (int t = 0; t < 9; t++) {
            if (t < 8) {
                #pragma unroll
                for (int jj = 0; jj < 2; jj++)
                    wreg[jj] = g_w3c[(t + 1) * 1024 + tid + 512 * jj];
            }
            if (wid < 8) {
                const int dy = t / 3 - 1, dx = t % 3 - 1;
                uint32_t bn[4];
                #pragma unroll
                for (int j = 0; j < 4; j++) {
                    int n = ng * 32 + j * 8 + dlt;
                    int img = n / 25, pos = n - img * 25;
                    int r = pos / 5, c = pos - r * 5;
                    int rr = r + dy, cc = c + dx;
                    bool ok = (n < 100) && ((unsigned)rr < 5u) && ((unsigned)cc < 5u);
                    bn[j] = ok ? (uint32_t)(S_POOL2 + (img * 25 + rr * 5 + cc) * 272 + 4 * q)
                               : (uint32_t)(S_ZERO + 4 * q);
                }
                gemm_tap<4, 8>(sm, (uint32_t)(S_WBUF + (t & 1) * 34816) + awlane, 272, bn, D0, D1);
            }
            if (t < 8) {
                uint32_t wb = S_WBUF + ((t + 1) & 1) * 34816;
                #pragma unroll
                for (int jj = 0; jj < 2; jj++) {
                    int u = tid + 512 * jj;
                    *(uint4*)(sm + wb + (u >> 4) * 272 + (u & 15) * 16) = wreg[jj];
                }
            }
            __syncthreads();
        }
        if (wid < 8) {
            #pragma unroll
            for (int mt = 0; mt < 2; mt++) {
                #pragma unroll
                for (int j = 0; j < 4; j++) {
                    float* c = mt ? D1[j] : D0[j];
                    int co = mg * 32 + mt * 16 + dlt;
                    int n0 = ng * 32 + j * 8 + 2 * q;
                    if (n0 < 100) {
                        float bA = s_b3[co], bB = s_b3[co + 8];
                        *(__nv_bfloat16*)(sm + S_ACT3 + n0 * 144 + co * 2) =
                            __float2bfloat16(fmaxf(c[0] + bA, 0.f));
                        *(__nv_bfloat16*)(sm + S_ACT3 + (n0 + 1) * 144 + co * 2) =
                            __float2bfloat16(fmaxf(c[1] + bA, 0.f));
                        *(__nv_bfloat16*)(sm + S_ACT3 + n0 * 144 + (co + 8) * 2) =
                            __float2bfloat16(fmaxf(c[2] + bB, 0.f));
                        *(__nv_bfloat16*)(sm + S_ACT3 + (n0 + 1) * 144 + (co + 8) * 2) =
                            __float2bfloat16(fmaxf(c[3] + bB, 0.f));
                    }
                }
            }
        }
        __syncthreads();
    }

    // ---- conv4: M=64, N=100, K=64/tap; warps 0..7 m32n32 ----
    {
        const int mg = (wid & 7) >> 2, ng = wid & 3;
        const uint32_t awlane = (uint32_t)((mg * 32 + dlt) * 144 + 4 * q);
        float D0[4][4], D1[4][4];
        #pragma unroll
        for (int j = 0; j < 4; j++)
            #pragma unroll
            for (int k = 0; k < 4; k++) { D0[j][k] = 0.f; D1[j][k] = 0.f; }

        uint4 wreg = g_w4c[tid];
        *(uint4*)(sm + S_WBUF + (tid >> 3) * 144 + (tid & 7) * 16) = wreg;
        __syncthreads();

        for (int t = 0; t < 9; t++) {
            if (t < 8) wreg = g_w4c[(t + 1) * 512 + tid];
            if (wid < 8) {
                const int dy = t / 3 - 1, dx = t % 3 - 1;
                uint32_t bn[4];
                #pragma unroll
                for (int j = 0; j < 4; j++) {
                    int n = ng * 32 + j * 8 + dlt;
                    int img = n / 25, pos = n - img * 25;
                    int r = pos / 5, c = pos - r * 5;
                    int rr = r + dy, cc = c + dx;
                    bool ok = (n < 100) && ((unsigned)rr < 5u) && ((unsigned)cc < 5u);
                    bn[j] = ok ? (uint32_t)(S_ACT3 + (img * 25 + rr * 5 + cc) * 144 + 4 * q)
                               : (uint32_t)(S_ZERO + 4 * q);
                }
                gemm_tap<4, 4>(sm, (uint32_t)(S_WBUF + (t & 1) * 34816) + awlane, 144, bn, D0, D1);
            }
            if (t < 8) {
                uint32_t wb = S_WBUF + ((t + 1) & 1) * 34816;
                *(uint4*)(sm + wb + (tid >> 3) * 144 + (tid & 7) * 16) = wreg;
            }
            __syncthreads();
        }
        if (wid < 8) {
            #pragma unroll
            for (int mt = 0; mt < 2; mt++) {
                #pragma unroll
                for (int j = 0; j < 4; j++) {
                    float* c = mt ? D1[j] : D0[j];
                    int co = mg * 32 + mt * 16 + dlt;
                    int n0 = ng * 32 + j * 8 + 2 * q;
                    if (n0 < 100) {
                        float bA = s_b4[co], bB = s_b4[co + 8];
                        __nv_bfloat162 v01 = __floats2bfloat162_rn(fmaxf(c[0] + bA, 0.f),
                                                                   fmaxf(c[1] + bA, 0.f));
                        __nv_bfloat162 v23 = __floats2bfloat162_rn(fmaxf(c[2] + bB, 0.f),
                                                                   fmaxf(c[3] + bB, 0.f));
                        *(uint32_t*)(sm + S_ACT4 + co * 208 + n0 * 2) = *(uint32_t*)&v01;
                        *(uint32_t*)(sm + S_ACT4 + (co + 8) * 208 + n0 * 2) = *(uint32_t*)&v23;
                    }
                }
            }
        }
        __syncthreads();
    }

    // ---- head: pool 2x2 -> mean -> dense -> sigmoid ----
    if (tid < 256) {
        int img = tid >> 6, c = tid & 63;
        const char* b = sm + S_ACT4 + c * 208 + img * 50;
        #define GA(p) __bfloat162float(*(const __nv_bfloat16*)(b + (p) * 2))
        float m00 = fmaxf(fmaxf(GA(0), GA(1)), fmaxf(GA(5), GA(6)));
        float m01 = fmaxf(fmaxf(GA(2), GA(3)), fmaxf(GA(7), GA(8)));
        float m10 = fmaxf(fmaxf(GA(10), GA(11)), fmaxf(GA(15), GA(16)));
        float m11 = fmaxf(fmaxf(GA(12), GA(13)), fmaxf(GA(17), GA(18)));
        #undef GA
        s_feat[img * 64 + c] = 0.25f * (m00 + m01 + m10 + m11);
    }
    __syncthreads();
    if (tid < 128) {
        int img = tid >> 5, jn = tid & 31;
        float acc = s_bd1[jn];
        #pragma unroll 8
        for (int c = 0; c < 64; c++) acc += s_feat[img * 64 + c] * __ldg(wd1 + c * 32 + jn);
        s_h[img * 32 + jn] = fmaxf(acc, 0.f);
    }
    __syncthreads();
    if (tid < 16) {
        int img = tid >> 2, k = tid & 3;
        float acc = s_bd2[k];
        #pragma unroll 8
        for (int j = 0; j < 32; j++) acc += s_h[img * 32 + j] * s_wd2[j * 4 + k];
        s_sv[img * 4 + k] = 1.f / (1.f + expf(-acc));
    }
    __syncthreads();
    if (tid < 4) {
        int gimg = blockIdx.x * 4 + tid;
        if (gimg < Btot) {
            const float* sv = s_sv + tid * 4;
            const float p1x = sv[0], p1y = sv[1], p2x = sv[2], p2y = sv[3];
            float px[5], py[5], pos[5];
            #pragma unroll
            for (int i = 0; i < 5; i++) {
                float t = 0.25f * (float)i;
                float x = rintf(((1.f - t) * p1x + t * p2x) * 10.f);
                float y = rintf(((1.f - t) * p1y + t * p2y) * 10.f);
                px[i] = x; py[i] = y;
                pos[i] = x * 10.f + y;
            }
            int ord[5] = {0, 1, 2, 3, 4};
            for (int i = 1; i < 5; i++) {
                int key = ord[i]; float kp = pos[key]; int j = i - 1;
                while (j >= 0 && pos[ord[j]] > kp) { ord[j + 1] = ord[j]; j--; }
                ord[j + 1] = key;
            }
            float ox[5], oy[5];
            #pragma unroll
            for (int i = 0; i < 5; i++) { ox[i] = px[ord[i]]; oy[i] = py[ord[i]]; }
            float o[10];
            #pragma unroll
            for (int i = 0; i < 10; i++) o[i] = -1.f;
            o[0] = ox[0]; o[1] = oy[0];
            int dst = 1;
            for (int i = 1; i < 5; i++) {
                float d = fabsf(ox[i] - ox[i - 1]) + fabsf(oy[i] - oy[i - 1]);
                if (d != 0.f) { o[2 * dst] = ox[i]; o[2 * dst + 1] = oy[i]; dst++; }
            }
            float* op = out + (long long)gimg * 10;
            #pragma unroll
            for (int i = 0; i < 10; i++) op[i] = o[i];
        }
    }
}

extern "C" void kernel_launch(void* const* d_in, const int* in_sizes, int n_in,
                              void* d_out, int out_size) {
    const float* data = (const float*)d_in[0];
    const float* w1   = (const float*)d_in[1];
    const float* b1   = (const float*)d_in[2];
    const float* w2   = (const float*)d_in[3];
    const float* b2   = (const float*)d_in[4];
    const float* w3   = (const float*)d_in[5];
    const float* b3   = (const float*)d_in[6];
    const float* w4   = (const float*)d_in[7];
    const float* b4   = (const float*)d_in[8];
    const float* wd1  = (const float*)d_in[9];
    const float* bd1  = (const float*)d_in[10];
    const float* wd2  = (const float*)d_in[11];
    const float* bd2  = (const float*)d_in[12];
    float* out = (float*)d_out;
    const int B = in_sizes[0] / 100;

    cudaFuncSetAttribute(img2svg_mma, cudaFuncAttributeMaxDynamicSharedMemorySize, SMEM_TOTAL);

    convert_weights<<<96, 256>>>(w2, w3, w4);
    img2svg_mma<<<(B + 3) / 4, NT, SMEM_TOTAL>>>(data, w1, b1, b2, b3, b4,
                                                 wd1, bd1, wd2, bd2, out, B);
}

// round 6
// speedup vs baseline: 5.5120x; 1.0177x over previous
#include <cuda_runtime.h>
#include <cuda_bf16.h>
#include <cstdint>

#define NT 512

// Transposed bf16 weights in gmem: [tap][co][ci] row-major
__device__ uint4 g_w2c[9 * 2048];  // [tap][128co][128ci]
__device__ uint4 g_w3c[9 * 1024];  // [tap][64co][128ci]
__device__ uint4 g_w4c[9 * 512];   // [tap][64co][64ci]

__global__ void convert_weights(const float* __restrict__ w2,
                                const float* __restrict__ w3,
                                const float* __restrict__ w4) {
    int gid = blockIdx.x * blockDim.x + threadIdx.x;
    int stride = gridDim.x * blockDim.x;
    __nv_bfloat16* p2 = (__nv_bfloat16*)g_w2c;
    __nv_bfloat16* p3 = (__nv_bfloat16*)g_w3c;
    __nv_bfloat16* p4 = (__nv_bfloat16*)g_w4c;
    for (int i = gid; i < 9 * 128 * 128; i += stride) {
        int tap = i >> 14, rem = i & 16383, co = rem >> 7, ci = rem & 127;
        p2[i] = __float2bfloat16(w2[tap * 16384 + ci * 128 + co]);
    }
    for (int i = gid; i < 9 * 64 * 128; i += stride) {
        int tap = i >> 13, rem = i & 8191, co = rem >> 7, ci = rem & 127;
        p3[i] = __float2bfloat16(w3[tap * 8192 + ci * 64 + co]);
    }
    for (int i = gid; i < 9 * 64 * 64; i += stride) {
        int tap = i >> 12, rem = i & 4095, co = rem >> 6, ci = rem & 63;
        p4[i] = __float2bfloat16(w4[tap * 4096 + ci * 64 + co]);
    }
}

// ---------------- SMEM layout (byte offsets) ----------------
#define S_ACT1   0          // 4 x [100 pos][136 ci] bf16 (stride 272B) = 108800
#define S_WBUF   108800     // 2 x 34816 weight double-buffer = 69632
#define S_POOL2  178432     // [100][136] bf16 stride 272 = 27200
#define S_ACT3   205632     // [100][72] bf16 stride 144 = 14400
#define S_ZERO   220032     // 272 zero row
#define S_B2     220304     // 128 f32
#define S_B3     220816     // 64 f32
#define S_B4     221072     // 64 f32
#define S_BD1    221328     // 32 f32
#define S_BD2    221456     // 4 f32
#define S_WD2    221472     // 128 f32
#define S_FEAT   221984     // 4*64 f32
#define S_H      223008     // 4*32 f32
#define S_SV     223520     // 16 f32
#define S_IMG    223584     // 400 f32
#define SMEM_TOTAL 225184
#define S_ACT4   54400      // act4 scratch [64co][104n] stride 208 (overlays act1 slot 2)

__device__ __forceinline__ uint32_t smem_u32(const void* p) {
    uint32_t a;
    asm("{ .reg .u64 t; cvta.to.shared.u64 t, %1; cvt.u32.u64 %0, t; }" : "=r"(a) : "l"(p));
    return a;
}

__device__ __forceinline__ void mma16816(float* c, uint32_t a0, uint32_t a1, uint32_t a2,
                                         uint32_t a3, uint32_t b0, uint32_t b1) {
    asm volatile(
        "mma.sync.aligned.m16n8k16.row.col.f32.bf16.bf16.f32 "
        "{%0,%1,%2,%3},{%4,%5,%6,%7},{%8,%9},{%0,%1,%2,%3};\n"
        : "+f"(c[0]), "+f"(c[1]), "+f"(c[2]), "+f"(c[3])
        : "r"(a0), "r"(a1), "r"(a2), "r"(a3), "r"(b0), "r"(b1));
}

// One tap via ldmatrix: C[m32][n = NJ*8] += W[m32][k] * Act[n][k], k = KS*16.
// aAddr: per-lane shared addr of A row (ldmatrix x4 layout); bAddr[j]: per-lane B row addrs.
template <int NJ, int KS>
__device__ __forceinline__ void gemm_tap(uint32_t aAddr, int ws, const uint32_t* bAddr,
                                         int njeff, float (*C0)[4], float (*C1)[4]) {
    #pragma unroll
    for (int ks = 0; ks < KS; ks++) {
        uint32_t a0, a1, a2, a3, a4, a5, a6, a7;
        asm volatile("ldmatrix.sync.aligned.m8n8.x4.shared.b16 {%0,%1,%2,%3},[%4];"
                     : "=r"(a0), "=r"(a1), "=r"(a2), "=r"(a3) : "r"(aAddr + 32 * ks));
        asm volatile("ldmatrix.sync.aligned.m8n8.x4.shared.b16 {%0,%1,%2,%3},[%4];"
                     : "=r"(a4), "=r"(a5), "=r"(a6), "=r"(a7) : "r"(aAddr + 16 * ws + 32 * ks));
        #pragma unroll
        for (int j = 0; j < NJ; j++) {
            if (j < njeff) {
                uint32_t b0, b1;
                asm volatile("ldmatrix.sync.aligned.m8n8.x2.shared.b16 {%0,%1},[%2];"
                             : "=r"(b0), "=r"(b1) : "r"(bAddr[j] + 32 * ks));
                mma16816(C0[j], a0, a1, a2, a3, b0, b1);
                mma16816(C1[j], a4, a5, a6, a7, b0, b1);
            }
        }
    }
}

__global__ __launch_bounds__(NT, 1)
void img2svg_mma(const float* __restrict__ data,
                 const float* __restrict__ w1, const float* __restrict__ b1,
                 const float* __restrict__ b2v, const float* __restrict__ b3v,
                 const float* __restrict__ b4v,
                 const float* __restrict__ wd1, const float* __restrict__ bd1,
                 const float* __restrict__ wd2, const float* __restrict__ bd2,
                 float* __restrict__ out, int Btot) {
    extern __shared__ char sm[];
    const int tid = threadIdx.x;
    const int wid = tid >> 5, lane = tid & 31;
    const int dlt = lane >> 2, q = lane & 3;
    const uint32_t sbase = smem_u32(sm);
    // ldmatrix lane roles
    const int rA = (lane & 7) + ((lane >> 3) & 1) * 8;   // A row within m16 group
    const int cA = (lane >> 4) * 16;                     // A k-byte offset
    const int rB = lane & 7;                             // B row (n)
    const int hB = ((lane >> 3) & 1) * 16;               // B k-byte offset

    float* s_b2  = (float*)(sm + S_B2);
    float* s_b3  = (float*)(sm + S_B3);
    float* s_b4  = (float*)(sm + S_B4);
    float* s_bd1 = (float*)(sm + S_BD1);
    float* s_bd2 = (float*)(sm + S_BD2);
    float* s_wd2 = (float*)(sm + S_WD2);
    float* s_feat = (float*)(sm + S_FEAT);
    float* s_h   = (float*)(sm + S_H);
    float* s_sv  = (float*)(sm + S_SV);
    float* s_img = (float*)(sm + S_IMG);

    // ---- init loads ----
    if (tid < 128) s_b2[tid] = b2v[tid];
    if (tid < 64)  s_b3[tid] = b3v[tid];
    if (tid < 64)  s_b4[tid] = b4v[tid];
    if (tid < 32)  s_bd1[tid] = bd1[tid];
    if (tid < 4)   s_bd2[tid] = bd2[tid];
    if (tid < 128) s_wd2[tid] = wd2[tid];
    if (tid < 68)  *(uint32_t*)(sm + S_ZERO + tid * 4) = 0u;
    {
        long long base = (long long)blockIdx.x * 400;
        for (int e = tid; e < 400; e += NT) {
            long long gi = base + e;
            s_img[e] = (gi < (long long)Btot * 100) ? data[gi] : 0.f;
        }
    }
    __syncthreads();

    // ---- conv1 (scalar): 1 -> 128, relu -> act1[img][pos][ci] bf16 ----
    {
        const int img = tid >> 7, co = tid & 127;
        const float* ip = s_img + img * 100;
        float wv[9];
        #pragma unroll
        for (int t = 0; t < 9; t++) wv[t] = w1[t * 128 + co];
        const float bias = b1[co];
        for (int pos = 0; pos < 100; pos++) {
            int r = pos / 10, c = pos - r * 10;
            float acc = bias;
            #pragma unroll
            for (int dy = -1; dy <= 1; dy++) {
                int rr = r + dy;
                if ((unsigned)rr < 10u) {
                    #pragma unroll
                    for (int dx = -1; dx <= 1; dx++) {
                        int cc = c + dx;
                        if ((unsigned)cc < 10u)
                            acc += wv[(dy + 1) * 3 + dx + 1] * ip[rr * 10 + cc];
                    }
                }
            }
            *(__nv_bfloat16*)(sm + S_ACT1 + (img * 100 + pos) * 272 + co * 2) =
                __float2bfloat16(fmaxf(acc, 0.f));
        }
    }
    __syncthreads();

    // ---- conv2: per pass 2 images x 8 warps, warp tile m32 x n64, K=128/tap ----
    for (int p = 0; p < 2; p++) {
        const int w8 = wid & 7;
        const int my_img = p * 2 + (wid >> 3);
        const int mg = w8 >> 1, ng = w8 & 1;
        const int njeff = ng ? 5 : 8;    // n-groups >= 104 are pure padding
        float C0[8][4], C1[8][4];
        #pragma unroll
        for (int j = 0; j < 8; j++)
            #pragma unroll
            for (int k = 0; k < 4; k++) { C0[j][k] = 0.f; C1[j][k] = 0.f; }

        uint4 wreg[4];
        #pragma unroll
        for (int jj = 0; jj < 4; jj++) wreg[jj] = g_w2c[tid + 512 * jj];
        #pragma unroll
        for (int jj = 0; jj < 4; jj++) {
            int u = tid + 512 * jj;
            *(uint4*)(sm + S_WBUF + (u >> 4) * 272 + (u & 15) * 16) = wreg[jj];
        }
        __syncthreads();

        for (int t = 0; t < 9; t++) {
            if (t < 8) {
                #pragma unroll
                for (int jj = 0; jj < 4; jj++)
                    wreg[jj] = g_w2c[(t + 1) * 2048 + tid + 512 * jj];
            }
            const int dy = t / 3 - 1, dx = t % 3 - 1;
            uint32_t bA[8];
            #pragma unroll
            for (int j = 0; j < 8; j++) {
                int n = ng * 64 + j * 8 + rB;
                int r = n / 10, c = n - r * 10;
                int rr = r + dy, cc = c + dx;
                bool ok = (n < 100) && ((unsigned)rr < 10u) && ((unsigned)cc < 10u);
                bA[j] = ok ? sbase + (uint32_t)(S_ACT1 + (my_img * 100 + rr * 10 + cc) * 272 + hB)
                           : sbase + (uint32_t)(S_ZERO + hB);
            }
            gemm_tap<8, 8>(sbase + (uint32_t)(S_WBUF + (t & 1) * 34816 + (mg * 32 + rA) * 272 + cA),
                           272, bA, njeff, C0, C1);
            if (t < 8) {
                uint32_t wb = S_WBUF + ((t + 1) & 1) * 34816;
                #pragma unroll
                for (int jj = 0; jj < 4; jj++) {
                    int u = tid + 512 * jj;
                    *(uint4*)(sm + wb + (u >> 4) * 272 + (u & 15) * 16) = wreg[jj];
                }
            }
            __syncthreads();
        }

        // epilogue: bias+relu -> scratch [co][104 n] (overlays act1 slot of my_img)
        const uint32_t scr = S_ACT1 + (uint32_t)my_img * 27200;
        #pragma unroll
        for (int mt = 0; mt < 2; mt++) {
            #pragma unroll
            for (int j = 0; j < 8; j++) {
                float* c = mt ? C1[j] : C0[j];
                int co = mg * 32 + mt * 16 + dlt;
                int n0 = ng * 64 + j * 8 + 2 * q;
                if (n0 < 100) {
                    float bAv = s_b2[co], bBv = s_b2[co + 8];
                    __nv_bfloat162 v01 = __floats2bfloat162_rn(fmaxf(c[0] + bAv, 0.f),
                                                               fmaxf(c[1] + bAv, 0.f));
                    __nv_bfloat162 v23 = __floats2bfloat162_rn(fmaxf(c[2] + bBv, 0.f),
                                                               fmaxf(c[3] + bBv, 0.f));
                    *(uint32_t*)(sm + scr + co * 208 + n0 * 2) = *(uint32_t*)&v01;
                    *(uint32_t*)(sm + scr + (co + 8) * 208 + n0 * 2) = *(uint32_t*)&v23;
                }
            }
        }
        __syncthreads();
        // 2x2 maxpool -> pooled2[img*25+pp][ci]
        {
            int t8 = (wid & 7) * 32 + lane;
            for (int e = t8; e < 3200; e += 256) {
                int co = e & 127, pp = e >> 7;
                int pr = pp / 5, pc = pp - pr * 5;
                int ntop = pr * 20 + pc * 2;
                uint32_t topw = *(uint32_t*)(sm + scr + co * 208 + ntop * 2);
                uint32_t botw = *(uint32_t*)(sm + scr + co * 208 + (ntop + 10) * 2);
                float2 tf = __bfloat1622float2(*(__nv_bfloat162*)&topw);
                float2 bf = __bfloat1622float2(*(__nv_bfloat162*)&botw);
                float m = fmaxf(fmaxf(tf.x, tf.y), fmaxf(bf.x, bf.y));
                *(__nv_bfloat16*)(sm + S_POOL2 + (my_img * 25 + pp) * 272 + co * 2) =
                    __float2bfloat16(m);
            }
        }
        __syncthreads();
    }

    // ---- conv3: M=64, N=100 (4img x 25pos), K=128/tap; ALL 16 warps m32n16 ----
    {
        const int mg = wid & 1, ng = wid >> 1;           // ng 0..7
        const int njeff = (ng < 6) ? 2 : ((ng == 6) ? 1 : 0);
        float D0[2][4], D1[2][4];
        #pragma unroll
        for (int j = 0; j < 2; j++)
            #pragma unroll
            for (int k = 0; k < 4; k++) { D0[j][k] = 0.f; D1[j][k] = 0.f; }

        uint4 wreg[2];
        #pragma unroll
        for (int jj = 0; jj < 2; jj++) wreg[jj] = g_w3c[tid + 512 * jj];
        #pragma unroll
        for (int jj = 0; jj < 2; jj++) {
            int u = tid + 512 * jj;
            *(uint4*)(sm + S_WBUF + (u >> 4) * 272 + (u & 15) * 16) = wreg[jj];
        }
        __syncthreads();

        for (int t = 0; t < 9; t++) {
            if (t < 8) {
                #pragma unroll
                for (int jj = 0; jj < 2; jj++)
                    wreg[jj] = g_w3c[(t + 1) * 1024 + tid + 512 * jj];
            }
            {
                const int dy = t / 3 - 1, dx = t % 3 - 1;
                uint32_t bA[2];
                #pragma unroll
                for (int j = 0; j < 2; j++) {
                    int n = ng * 16 + j * 8 + rB;
                    int img = n / 25, pos = n - img * 25;
                    int r = pos / 5, c = pos - r * 5;
                    int rr = r + dy, cc = c + dx;
                    bool ok = (n < 100) && ((unsigned)rr < 5u) && ((unsigned)cc < 5u);
                    bA[j] = ok ? sbase + (uint32_t)(S_POOL2 + (img * 25 + rr * 5 + cc) * 272 + hB)
                               : sbase + (uint32_t)(S_ZERO + hB);
                }
                gemm_tap<2, 8>(sbase + (uint32_t)(S_WBUF + (t & 1) * 34816 + (mg * 32 + rA) * 272 + cA),
                               272, bA, njeff, D0, D1);
            }
            if (t < 8) {
                uint32_t wb = S_WBUF + ((t + 1) & 1) * 34816;
                #pragma unroll
                for (int jj = 0; jj < 2; jj++) {
                    int u = tid + 512 * jj;
                    *(uint4*)(sm + wb + (u >> 4) * 272 + (u & 15) * 16) = wreg[jj];
                }
            }
            __syncthreads();
        }
        #pragma unroll
        for (int mt = 0; mt < 2; mt++) {
            #pragma unroll
            for (int j = 0; j < 2; j++) {
                float* c = mt ? D1[j] : D0[j];
                int co = mg * 32 + mt * 16 + dlt;
                int n0 = ng * 16 + j * 8 + 2 * q;
                if (n0 < 100) {
                    float bAv = s_b3[co], bBv = s_b3[co + 8];
                    *(__nv_bfloat16*)(sm + S_ACT3 + n0 * 144 + co * 2) =
                        __float2bfloat16(fmaxf(c[0] + bAv, 0.f));
                    *(__nv_bfloat16*)(sm + S_ACT3 + (n0 + 1) * 144 + co * 2) =
                        __float2bfloat16(fmaxf(c[1] + bAv, 0.f));
                    *(__nv_bfloat16*)(sm + S_ACT3 + n0 * 144 + (co + 8) * 2) =
                        __float2bfloat16(fmaxf(c[2] + bBv, 0.f));
                    *(__nv_bfloat16*)(sm + S_ACT3 + (n0 + 1) * 144 + (co + 8) * 2) =
                        __float2bfloat16(fmaxf(c[3] + bBv, 0.f));
                }
            }
        }
        __syncthreads();
    }

    // ---- conv4: M=64, N=100, K=64/tap; ALL 16 warps m32n16 ----
    {
        const int mg = wid & 1, ng = wid >> 1;
        const int njeff = (ng < 6) ? 2 : ((ng == 6) ? 1 : 0);
        float D0[2][4], D1[2][4];
        #pragma unroll
        for (int j = 0; j < 2; j++)
            #pragma unroll
            for (int k = 0; k < 4; k++) { D0[j][k] = 0.f; D1[j][k] = 0.f; }

        uint4 wreg = g_w4c[tid];
        *(uint4*)(sm + S_WBUF + (tid >> 3) * 144 + (tid & 7) * 16) = wreg;
        __syncthreads();

        for (int t = 0; t < 9; t++) {
            if (t < 8) wreg = g_w4c[(t + 1) * 512 + tid];
            {
                const int dy = t / 3 - 1, dx = t % 3 - 1;
                uint32_t bA[2];
                #pragma unroll
                for (int j = 0; j < 2; j++) {
                    int n = ng * 16 + j * 8 + rB;
                    int img = n / 25, pos = n - img * 25;
                    int r = pos / 5, c = pos - r * 5;
                    int rr = r + dy, cc = c + dx;
                    bool ok = (n < 100) && ((unsigned)rr < 5u) && ((unsigned)cc < 5u);
                    bA[j] = ok ? sbase + (uint32_t)(S_ACT3 + (img * 25 + rr * 5 + cc) * 144 + hB)
                               : sbase + (uint32_t)(S_ZERO + hB);
                }
                gemm_tap<2, 4>(sbase + (uint32_t)(S_WBUF + (t & 1) * 34816 + (mg * 32 + rA) * 144 + cA),
                               144, bA, njeff, D0, D1);
            }
            if (t < 8) {
                uint32_t wb = S_WBUF + ((t + 1) & 1) * 34816;
                *(uint4*)(sm + wb + (tid >> 3) * 144 + (tid & 7) * 16) = wreg;
            }
            __syncthreads();
        }
        #pragma unroll
        for (int mt = 0; mt < 2; mt++) {
            #pragma unroll
            for (int j = 0; j < 2; j++) {
                float* c = mt ? D1[j] : D0[j];
                int co = mg * 32 + mt * 16 + dlt;
                int n0 = ng * 16 + j * 8 + 2 * q;
                if (n0 < 100) {
                    float bAv = s_b4[co], bBv = s_b4[co + 8];
                    __nv_bfloat162 v01 = __floats2bfloat162_rn(fmaxf(c[0] + bAv, 0.f),
                                                               fmaxf(c[1] + bAv, 0.f));
                    __nv_bfloat162 v23 = __floats2bfloat162_rn(fmaxf(c[2] + bBv, 0.f),
                                                               fmaxf(c[3] + bBv, 0.f));
                    *(uint32_t*)(sm + S_ACT4 + co * 208 + n0 * 2) = *(uint32_t*)&v01;
                    *(uint32_t*)(sm + S_ACT4 + (co + 8) * 208 + n0 * 2) = *(uint32_t*)&v23;
                }
            }
        }
        __syncthreads();
    }

    // ---- head: pool 2x2 -> mean -> dense -> sigmoid ----
    if (tid < 256) {
        int img = tid >> 6, c = tid & 63;
        const char* b = sm + S_ACT4 + c * 208 + img * 50;
        #define GA(p) __bfloat162float(*(const __nv_bfloat16*)(b + (p) * 2))
        float m00 = fmaxf(fmaxf(GA(0), GA(1)), fmaxf(GA(5), GA(6)));
        float m01 = fmaxf(fmaxf(GA(2), GA(3)), fmaxf(GA(7), GA(8)));
        float m10 = fmaxf(fmaxf(GA(10), GA(11)), fmaxf(GA(15), GA(16)));
        float m11 = fmaxf(fmaxf(GA(12), GA(13)), fmaxf(GA(17), GA(18)));
        #undef GA
        s_feat[img * 64 + c] = 0.25f * (m00 + m01 + m10 + m11);
    }
    __syncthreads();
    if (tid < 128) {
        int img = tid >> 5, jn = tid & 31;
        float acc = s_bd1[jn];
        #pragma unroll 8
        for (int c = 0; c < 64; c++) acc += s_feat[img * 64 + c] * __ldg(wd1 + c * 32 + jn);
        s_h[img * 32 + jn] = fmaxf(acc, 0.f);
    }
    __syncthreads();
    if (tid < 16) {
        int img = tid >> 2, k = tid & 3;
        float acc = s_bd2[k];
        #pragma unroll 8
        for (int j = 0; j < 32; j++) acc += s_h[img * 32 + j] * s_wd2[j * 4 + k];
        s_sv[img * 4 + k] = 1.f / (1.f + expf(-acc));
    }
    __syncthreads();
    if (tid < 4) {
        int gimg = blockIdx.x * 4 + tid;
        if (gimg < Btot) {
            const float* sv = s_sv + tid * 4;
            const float p1x = sv[0], p1y = sv[1], p2x = sv[2], p2y = sv[3];
            float px[5], py[5], pos[5];
            #pragma unroll
            for (int i = 0; i < 5; i++) {
                float t = 0.25f * (float)i;
                float x = rintf(((1.f - t) * p1x + t * p2x) * 10.f);
                float y = rintf(((1.f - t) * p1y + t * p2y) * 10.f);
                px[i] = x; py[i] = y;
                pos[i] = x * 10.f + y;
            }
            int ord[5] = {0, 1, 2, 3, 4};
            for (int i = 1; i < 5; i++) {
                int key = ord[i]; float kp = pos[key]; int j = i - 1;
                while (j >= 0 && pos[ord[j]] > kp) { ord[j + 1] = ord[j]; j--; }
                ord[j + 1] = key;
            }
            float ox[5], oy[5];
            #pragma unroll
            for (int i = 0; i < 5; i++) { ox[i] = px[ord[i]]; oy[i] = py[ord[i]]; }
            float o[10];
            #pragma unroll
            for (int i = 0; i < 10; i++) o[i] = -1.f;
            o[0] = ox[0]; o[1] = oy[0];
            int dst = 1;
            for (int i = 1; i < 5; i++) {
                float d = fabsf(ox[i] - ox[i - 1]) + fabsf(oy[i] - oy[i - 1]);
                if (d != 0.f) { o[2 * dst] = ox[i]; o[2 * dst + 1] = oy[i]; dst++; }
            }
            float* op = out + (long long)gimg * 10;
            #pragma unroll
            for (int i = 0; i < 10; i++) op[i] = o[i];
        }
    }
}

extern "C" void kernel_launch(void* const* d_in, const int* in_sizes, int n_in,
                              void* d_out, int out_size) {
    const float* data = (const float*)d_in[0];
    const float* w1   = (const float*)d_in[1];
    const float* b1   = (const float*)d_in[2];
    const float* w2   = (const float*)d_in[3];
    const float* b2   = (const float*)d_in[4];
    const float* w3   = (const float*)d_in[5];
    const float* b3   = (const float*)d_in[6];
    const float* w4   = (const float*)d_in[7];
    const float* b4   = (const float*)d_in[8];
    const float* wd1  = (const float*)d_in[9];
    const float* bd1  = (const float*)d_in[10];
    const float* wd2  = (const float*)d_in[11];
    const float* bd2  = (const float*)d_in[12];
    float* out = (float*)d_out;
    const int B = in_sizes[0] / 100;

    cudaFuncSetAttribute(img2svg_mma, cudaFuncAttributeMaxDynamicSharedMemorySize, SMEM_TOTAL);

    convert_weights<<<96, 256>>>(w2, w3, w4);
    img2svg_mma<<<(B + 3) / 4, NT, SMEM_TOTAL>>>(data, w1, b1, b2, b3, b4,
                                                 wd1, bd1, wd2, bd2, out, B);
}